// round 8
// baseline (speedup 1.0000x reference)
#include <cuda_runtime.h>
#include <cuda_bf16.h>
#include <cuda_fp16.h>
#include <math.h>

#define B_   16
#define NQ_  300
#define C_   256
#define H_   8
#define DH_  32
#define L_   3
#define P_   4
#define DFF_ 2048
#define LEN_IN_ 21504
#define MTGT (B_*NQ_)      // 4800
#define MV   (B_*LEN_IN_)  // 344064

// ---------------- scratch (device globals; no allocation allowed) ----------
__device__ float g_t2  [MTGT*C_];
__device__ float g_qk  [MTGT*C_];
__device__ float g_qkv [MTGT*3*C_];
__device__ float g_sa  [MTGT*C_];
__device__ float g_tgt1[MTGT*C_];
__device__ float g_tgt2[MTGT*C_];
__device__ float g_v   [(size_t)MV*C_];
__device__ float g_off [MTGT*H_*L_*P_*2];
__device__ float g_aw  [MTGT*H_*L_*P_];
__device__ float g_ca  [MTGT*C_];
__device__ __half g_t2h [MTGT*C_];
__device__ __half g_hidh[MTGT*DFF_];
__device__ __half g_wvh [C_*C_];
__device__ __half g_w1h [DFF_*C_];
__device__ __half g_w2h [C_*DFF_];

// ---------------- fp32 -> fp16 convert (weights) ---------------------------
__global__ void __launch_bounds__(256) cvt_kernel(
    const float* __restrict__ x, __half* __restrict__ y, int n)
{
    int i = (blockIdx.x * 256 + threadIdx.x) * 4;
    if (i < n) {
        float4 v = *(const float4*)(x + i);
        __half2 lo = __floats2half2_rn(v.x, v.y);
        __half2 hi = __floats2half2_rn(v.z, v.w);
        uint2 o; o.x = *(unsigned*)&lo; o.y = *(unsigned*)&hi;
        *(uint2*)(y + i) = o;
    }
}

// ---------------- LayerNorm (+ optional pos add / fp16 out) ----------------
__global__ void __launch_bounds__(256) ln_kernel(
    const float* __restrict__ x, const float* __restrict__ g,
    const float* __restrict__ b, const float* __restrict__ pos,
    float* __restrict__ t2, float* __restrict__ qk, __half* __restrict__ t2h)
{
    int row = blockIdx.x;
    int tid = threadIdx.x;
    size_t idx = (size_t)row * C_ + tid;
    float v = x[idx];

    __shared__ float red[8];
    float s = v;
    #pragma unroll
    for (int o = 16; o; o >>= 1) s += __shfl_xor_sync(0xffffffffu, s, o);
    if ((tid & 31) == 0) red[tid >> 5] = s;
    __syncthreads();
    float tot = 0.f;
    #pragma unroll
    for (int i = 0; i < 8; i++) tot += red[i];
    float mu = tot * (1.f / 256.f);
    float d = v - mu;
    __syncthreads();
    float s2 = d * d;
    #pragma unroll
    for (int o = 16; o; o >>= 1) s2 += __shfl_xor_sync(0xffffffffu, s2, o);
    if ((tid & 31) == 0) red[tid >> 5] = s2;
    __syncthreads();
    float tot2 = 0.f;
    #pragma unroll
    for (int i = 0; i < 8; i++) tot2 += red[i];
    float var = tot2 * (1.f / 256.f);

    float y = d * rsqrtf(var + 1e-5f) * g[tid] + b[tid];
    if (t2)  t2[idx] = y;
    if (t2h) t2h[idx] = __float2half_rn(y);
    if (pos) qk[idx] = y + pos[idx];
}

// ======================= MMA helpers =======================================
__device__ __forceinline__ void mma_bf16(
    float& c0, float& c1, float& c2, float& c3,
    unsigned a0, unsigned a1, unsigned a2, unsigned a3,
    unsigned b0, unsigned b1)
{
    asm volatile(
        "mma.sync.aligned.m16n8k16.row.col.f32.bf16.bf16.f32 "
        "{%0,%1,%2,%3}, {%4,%5,%6,%7}, {%8,%9}, {%0,%1,%2,%3};"
        : "+f"(c0), "+f"(c1), "+f"(c2), "+f"(c3)
        : "r"(a0), "r"(a1), "r"(a2), "r"(a3), "r"(b0), "r"(b1));
}

__device__ __forceinline__ void mma_f16(
    float& c0, float& c1, float& c2, float& c3,
    unsigned a0, unsigned a1, unsigned a2, unsigned a3,
    unsigned b0, unsigned b1)
{
    asm volatile(
        "mma.sync.aligned.m16n8k16.row.col.f32.f16.f16.f32 "
        "{%0,%1,%2,%3}, {%4,%5,%6,%7}, {%8,%9}, {%0,%1,%2,%3};"
        : "+f"(c0), "+f"(c1), "+f"(c2), "+f"(c3)
        : "r"(a0), "r"(a1), "r"(a2), "r"(a3), "r"(b0), "r"(b1));
}

__device__ __forceinline__ void split2(float e0, float e1,
                                       unsigned& hi, unsigned& lo)
{
    __nv_bfloat16 h0 = __float2bfloat16_rn(e0);
    __nv_bfloat16 h1 = __float2bfloat16_rn(e1);
    float r0 = e0 - __bfloat162float(h0);
    float r1 = e1 - __bfloat162float(h1);
    __nv_bfloat162 hp; hp.x = h0; hp.y = h1;
    __nv_bfloat162 lp = __floats2bfloat162_rn(r0, r1);
    hi = *(unsigned*)&hp;
    lo = *(unsigned*)&lp;
}

__device__ __forceinline__ unsigned pack_h2(float e0, float e1)
{
    __half2 h = __floats2half2_rn(e0, e1);
    return *(unsigned*)&h;
}

// ======================= bf16x3 tensor-core GEMM ===========================
// C[M,N] = A[M,K] @ W[N,K]^T + bias. Tile 128x64x16, 8 warps, warp 32x32.
// epi: 0=bias  1=bias+relu  2=bias+residual
__global__ void __launch_bounds__(256, 2) gemm_mma(
    const float* __restrict__ A, const float* __restrict__ W,
    const float* __restrict__ bias, const float* __restrict__ resid,
    float* __restrict__ Cc, int M, int N, int K, int ldc, int coloff, int epi)
{
    __shared__ __align__(16) unsigned AsH[8*32*4];
    __shared__ __align__(16) unsigned AsL[8*32*4];
    __shared__ __align__(16) unsigned BsH[4*32*2*2];
    __shared__ __align__(16) unsigned BsL[4*32*2*2];

    int tid = threadIdx.x;
    int wid = tid >> 5, lane = tid & 31;
    int wm = wid & 3, wn = wid >> 2;
    int row0 = blockIdx.y * 128;
    int col0 = blockIdx.x * 64;

    int arow = tid >> 1;
    int ak0  = (tid & 1) * 8;
    int brow = tid >> 2;
    int bk0  = (tid & 3) * 4;

    int grow = row0 + arow;
    int gcol = col0 + brow;
    bool avalid = grow < M;
    bool bvalid = gcol < N;
    const float* Aptr = A + (size_t)grow * K + ak0;
    const float* Wptr = W + (size_t)gcol * K + bk0;

    int a_mt = arow >> 4;
    int a_g  = arow & 15;
    int a_laneg = a_g & 7;
    int a_regrow = a_g >> 3;
    int b_nt  = brow >> 3;
    int b_g   = brow & 7;
    int b_pair = b_nt >> 1;
    int b_sub  = b_nt & 1;

    float acc[2][4][4];
    #pragma unroll
    for (int i = 0; i < 2; i++)
        #pragma unroll
        for (int j = 0; j < 4; j++)
            #pragma unroll
            for (int r = 0; r < 4; r++) acc[i][j][r] = 0.f;

    float4 zf4 = make_float4(0.f, 0.f, 0.f, 0.f);
    float4 aR0 = avalid ? *(const float4*)(Aptr)     : zf4;
    float4 aR1 = avalid ? *(const float4*)(Aptr + 4) : zf4;
    float4 bR0 = bvalid ? *(const float4*)(Wptr)     : zf4;

    for (int kt = 0; kt < K; kt += 16) {
        {
            int reg = a_regrow + 2 * (ak0 >> 3);
            int t4  = (ak0 & 7) >> 1;
            unsigned hi, lo;
            int base = (a_mt * 32 + a_laneg * 4 + t4) * 4 + reg;
            split2(aR0.x, aR0.y, hi, lo); AsH[base] = hi; AsL[base] = lo;
            base = (a_mt * 32 + a_laneg * 4 + t4 + 1) * 4 + reg;
            split2(aR0.z, aR0.w, hi, lo); AsH[base] = hi; AsL[base] = lo;
            int ak1 = ak0 + 4;
            reg = a_regrow + 2 * (ak1 >> 3);
            t4  = (ak1 & 7) >> 1;
            base = (a_mt * 32 + a_laneg * 4 + t4) * 4 + reg;
            split2(aR1.x, aR1.y, hi, lo); AsH[base] = hi; AsL[base] = lo;
            base = (a_mt * 32 + a_laneg * 4 + t4 + 1) * 4 + reg;
            split2(aR1.z, aR1.w, hi, lo); AsH[base] = hi; AsL[base] = lo;
            int breg = bk0 >> 3;
            int bt4  = (bk0 & 7) >> 1;
            base = ((b_pair * 32 + b_g * 4 + bt4) * 2 + b_sub) * 2 + breg;
            split2(bR0.x, bR0.y, hi, lo); BsH[base] = hi; BsL[base] = lo;
            base = ((b_pair * 32 + b_g * 4 + bt4 + 1) * 2 + b_sub) * 2 + breg;
            split2(bR0.z, bR0.w, hi, lo); BsH[base] = hi; BsL[base] = lo;
        }
        __syncthreads();

        if (kt + 16 < K) {
            aR0 = avalid ? *(const float4*)(Aptr + kt + 16)     : zf4;
            aR1 = avalid ? *(const float4*)(Aptr + kt + 16 + 4) : zf4;
            bR0 = bvalid ? *(const float4*)(Wptr + kt + 16)     : zf4;
        }

        uint4 aH[2], aL[2], bH[2], bL[2];
        #pragma unroll
        for (int mt = 0; mt < 2; mt++) {
            int idx = ((wm * 2 + mt) * 32 + lane) * 4;
            aH[mt] = *(const uint4*)&AsH[idx];
            aL[mt] = *(const uint4*)&AsL[idx];
        }
        #pragma unroll
        for (int np = 0; np < 2; np++) {
            int idx = ((wn * 2 + np) * 32 + lane) * 4;
            bH[np] = *(const uint4*)&BsH[idx];
            bL[np] = *(const uint4*)&BsL[idx];
        }
        #pragma unroll
        for (int mt = 0; mt < 2; mt++) {
            #pragma unroll
            for (int nt = 0; nt < 4; nt++) {
                int np = nt >> 1, sub = nt & 1;
                unsigned bh0 = sub ? bH[np].z : bH[np].x;
                unsigned bh1 = sub ? bH[np].w : bH[np].y;
                unsigned bl0 = sub ? bL[np].z : bL[np].x;
                unsigned bl1 = sub ? bL[np].w : bL[np].y;
                float* c = acc[mt][nt];
                mma_bf16(c[0], c[1], c[2], c[3],
                         aH[mt].x, aH[mt].y, aH[mt].z, aH[mt].w, bh0, bh1);
                mma_bf16(c[0], c[1], c[2], c[3],
                         aH[mt].x, aH[mt].y, aH[mt].z, aH[mt].w, bl0, bl1);
                mma_bf16(c[0], c[1], c[2], c[3],
                         aL[mt].x, aL[mt].y, aL[mt].z, aL[mt].w, bh0, bh1);
            }
        }
        __syncthreads();
    }

    int g = lane >> 2, t4 = lane & 3;
    #pragma unroll
    for (int mt = 0; mt < 2; mt++) {
        #pragma unroll
        for (int nt = 0; nt < 4; nt++) {
            int r = row0 + wm * 32 + mt * 16 + g;
            int c = col0 + wn * 32 + nt * 8 + t4 * 2;
            if (c >= N) continue;
            float b0 = bias[c], b1 = bias[c + 1];
            #pragma unroll
            for (int half = 0; half < 2; half++) {
                int rr = r + half * 8;
                if (rr >= M) continue;
                float v0 = acc[mt][nt][half * 2 + 0] + b0;
                float v1 = acc[mt][nt][half * 2 + 1] + b1;
                if (epi == 1) { v0 = fmaxf(v0, 0.f); v1 = fmaxf(v1, 0.f); }
                else if (epi == 2) {
                    const float* rp = resid + (size_t)rr * ldc + coloff + c;
                    v0 += rp[0]; v1 += rp[1];
                }
                float2 o; o.x = v0; o.y = v1;
                *(float2*)(Cc + (size_t)rr * ldc + coloff + c) = o;
            }
        }
    }
}

// ======================= fp16x1 GEMM v2 ====================================
// BK=32, double-buffered fragment smem (1 sync / 32-k), fp16 weights.
// AH: A is fp16; OH: output fp16.  epi: 1=relu 2=residual 3=mask-zero
template<bool AH, bool OH>
__global__ void __launch_bounds__(256, 2) gemm_f16v(
    const void* __restrict__ Av, const __half* __restrict__ Wh,
    const float* __restrict__ bias, const float* __restrict__ resid,
    const unsigned char* __restrict__ mask,
    void* __restrict__ Cv, int M, int N, int K, int epi)
{
    __shared__ __align__(16) unsigned As[2][8*32*8];
    __shared__ __align__(16) unsigned Bs[2][4*32*2*4];

    int tid = threadIdx.x;
    int wid = tid >> 5, lane = tid & 31;
    int wm = wid & 3, wn = wid >> 2;
    int row0 = blockIdx.y * 128;
    int col0 = blockIdx.x * 64;

    // A staging: thread covers (arow, k 16-block kb_a) -> 16 halves / 16 floats
    int arow = tid >> 1;
    int kb_a = tid & 1;
    int a_mt = arow >> 4;
    int a_g  = arow & 15;
    int a_laneg = a_g & 7;
    int a_regrow = a_g >> 3;
    // B staging: thread covers (brow, 8 k at bk0)
    int brow = tid >> 2;
    int bk0  = (tid & 3) * 8;
    int b_nt = brow >> 3;
    int b_g  = brow & 7;
    int b_pair = b_nt >> 1;
    int b_sub  = b_nt & 1;
    int b_kb   = bk0 >> 4;
    int b_reg  = (bk0 >> 3) & 1;

    int grow = row0 + arow;
    int gcol = col0 + brow;
    bool avalid = grow < M;
    bool bvalid = gcol < N;

    const __half* Aph = AH ? ((const __half*)Av + (size_t)grow * K + kb_a * 16) : nullptr;
    const float*  Apf = AH ? nullptr : ((const float*)Av + (size_t)grow * K + kb_a * 16);
    const __half* Wp  = Wh + (size_t)gcol * K + bk0;

    float acc[2][4][4];
    #pragma unroll
    for (int i = 0; i < 2; i++)
        #pragma unroll
        for (int j = 0; j < 4; j++)
            #pragma unroll
            for (int r = 0; r < 4; r++) acc[i][j][r] = 0.f;

    uint4  aUa, aUb;                // fp16 A: 16 halves = 2x uint4
    float4 aF4[4];                  // fp32 A: 16 floats
    uint4  bU;                      // 8 halves of W
    float4 zf4 = make_float4(0.f, 0.f, 0.f, 0.f);
    uint4  zu4 = make_uint4(0, 0, 0, 0);

    // prefetch stage 0
    if (AH) {
        aUa = avalid ? *(const uint4*)(Aph)     : zu4;
        aUb = avalid ? *(const uint4*)(Aph + 8) : zu4;
    } else {
        #pragma unroll
        for (int j = 0; j < 4; j++)
            aF4[j] = avalid ? *(const float4*)(Apf + j * 4) : zf4;
    }
    bU = bvalid ? *(const uint4*)(Wp) : zu4;

    int p = 0;
    for (int kt = 0; kt < K; kt += 32) {
        // ---- store staged regs to fragment smem
        if (AH) {
            unsigned au[8];
            *(uint4*)&au[0] = aUa;
            *(uint4*)&au[4] = aUb;
            #pragma unroll
            for (int j = 0; j < 8; j++) {
                As[p][(a_mt * 32 + a_laneg * 4 + (j & 3)) * 8 + kb_a * 4
                      + a_regrow + 2 * (j >> 2)] = au[j];
            }
        } else {
            #pragma unroll
            for (int j = 0; j < 4; j++) {
                int pr0 = 2 * j, pr1 = 2 * j + 1;
                As[p][(a_mt * 32 + a_laneg * 4 + (pr0 & 3)) * 8 + kb_a * 4
                      + a_regrow + 2 * (pr0 >> 2)] = pack_h2(aF4[j].x, aF4[j].y);
                As[p][(a_mt * 32 + a_laneg * 4 + (pr1 & 3)) * 8 + kb_a * 4
                      + a_regrow + 2 * (pr1 >> 2)] = pack_h2(aF4[j].z, aF4[j].w);
            }
        }
        {
            const unsigned* bu = (const unsigned*)&bU;
            #pragma unroll
            for (int j = 0; j < 4; j++) {
                Bs[p][((b_pair * 32 + b_g * 4 + j) * 2 + b_sub) * 4
                      + b_kb * 2 + b_reg] = bu[j];
            }
        }
        __syncthreads();

        // ---- prefetch next stage
        if (kt + 32 < K) {
            if (AH) {
                aUa = avalid ? *(const uint4*)(Aph + kt + 32)     : zu4;
                aUb = avalid ? *(const uint4*)(Aph + kt + 32 + 8) : zu4;
            } else {
                #pragma unroll
                for (int j = 0; j < 4; j++)
                    aF4[j] = avalid ? *(const float4*)(Apf + kt + 32 + j * 4) : zf4;
            }
            bU = bvalid ? *(const uint4*)(Wp + kt + 32) : zu4;
        }

        // ---- consume fragments
        uint4 aF[2][2];
        #pragma unroll
        for (int mt = 0; mt < 2; mt++)
            #pragma unroll
            for (int kb = 0; kb < 2; kb++)
                aF[mt][kb] = *(const uint4*)&As[p][((wm * 2 + mt) * 32 + lane) * 8 + kb * 4];
        uint4 bF[2][2];
        #pragma unroll
        for (int np = 0; np < 2; np++)
            #pragma unroll
            for (int sub = 0; sub < 2; sub++)
                bF[np][sub] = *(const uint4*)&Bs[p][(((wn * 2 + np) * 32 + lane) * 2 + sub) * 4];

        #pragma unroll
        for (int mt = 0; mt < 2; mt++) {
            #pragma unroll
            for (int nt = 0; nt < 4; nt++) {
                int np = nt >> 1, sub = nt & 1;
                float* c = acc[mt][nt];
                mma_f16(c[0], c[1], c[2], c[3],
                        aF[mt][0].x, aF[mt][0].y, aF[mt][0].z, aF[mt][0].w,
                        bF[np][sub].x, bF[np][sub].y);
                mma_f16(c[0], c[1], c[2], c[3],
                        aF[mt][1].x, aF[mt][1].y, aF[mt][1].z, aF[mt][1].w,
                        bF[np][sub].z, bF[np][sub].w);
            }
        }
        p ^= 1;
    }

    // ---- epilogue
    int g = lane >> 2, t4 = lane & 3;
    #pragma unroll
    for (int mt = 0; mt < 2; mt++) {
        #pragma unroll
        for (int nt = 0; nt < 4; nt++) {
            int r = row0 + wm * 32 + mt * 16 + g;
            int c = col0 + wn * 32 + nt * 8 + t4 * 2;
            if (c >= N) continue;
            float b0 = bias[c], b1 = bias[c + 1];
            #pragma unroll
            for (int half = 0; half < 2; half++) {
                int rr = r + half * 8;
                if (rr >= M) continue;
                float v0 = acc[mt][nt][half * 2 + 0] + b0;
                float v1 = acc[mt][nt][half * 2 + 1] + b1;
                if (epi == 1) { v0 = fmaxf(v0, 0.f); v1 = fmaxf(v1, 0.f); }
                else if (epi == 2) {
                    const float* rp = resid + (size_t)rr * N + c;
                    v0 += rp[0]; v1 += rp[1];
                }
                else if (epi == 3 && mask[rr]) { v0 = 0.f; v1 = 0.f; }
                if (OH) {
                    __half2 o = __floats2half2_rn(v0, v1);
                    *(__half2*)((__half*)Cv + (size_t)rr * N + c) = o;
                } else {
                    float2 o; o.x = v0; o.y = v1;
                    *(float2*)((float*)Cv + (size_t)rr * N + c) = o;
                }
            }
        }
    }
}

// ---------------- Self-attention (split-k flash: 2 threads per q) ----------
__global__ void __launch_bounds__(256) attn_kernel(
    const float* __restrict__ qkv, float* __restrict__ sa)
{
    int b = blockIdx.x / H_;
    int h = blockIdx.x % H_;
    int q0 = blockIdx.y * 128;
    extern __shared__ float sm[];
    float* Ks = sm;
    float* Vs = sm + NQ_ * DH_;
    int tid = threadIdx.x;

    for (int i = tid; i < NQ_ * DH_; i += 256) {
        int r = i >> 5, d = i & 31;
        const float* base = qkv + ((size_t)(b * NQ_ + r)) * 768 + h * 32 + d;
        Ks[i] = base[256];
        Vs[i] = base[512];
    }
    __syncthreads();

    int q  = q0 + (tid >> 1);
    int hf = tid & 1;

    float m = -1e30f, s = 0.f;
    float acc[32];
    #pragma unroll
    for (int d = 0; d < 32; d++) acc[d] = 0.f;

    if (q < NQ_) {
        float4 qv[8];
        const float4* qb = (const float4*)(qkv + ((size_t)(b * NQ_ + q)) * 768 + h * 32);
        #pragma unroll
        for (int u = 0; u < 8; u++) qv[u] = qb[u];

        int kbeg = hf * 150, kend = kbeg + 150;
        for (int k = kbeg; k < kend; k++) {
            const float4* kb = (const float4*)(Ks + k * 32);
            float dot = 0.f;
            #pragma unroll
            for (int u = 0; u < 8; u++) {
                float4 kv = kb[u];
                dot += qv[u].x * kv.x + qv[u].y * kv.y + qv[u].z * kv.z + qv[u].w * kv.w;
            }
            dot *= 0.17677669529663687f;   // 1/sqrt(32)
            float nm = fmaxf(m, dot);
            float corr = __expf(m - nm);
            float e = __expf(dot - nm);
            s = s * corr + e;
            const float4* vb = (const float4*)(Vs + k * 32);
            #pragma unroll
            for (int u = 0; u < 8; u++) {
                float4 vv = vb[u];
                acc[4*u+0] = acc[4*u+0] * corr + e * vv.x;
                acc[4*u+1] = acc[4*u+1] * corr + e * vv.y;
                acc[4*u+2] = acc[4*u+2] * corr + e * vv.z;
                acc[4*u+3] = acc[4*u+3] * corr + e * vv.w;
            }
            m = nm;
        }
    }

    // merge partner halves (lanes differ by 1)
    float m_o = __shfl_xor_sync(0xffffffffu, m, 1);
    float s_o = __shfl_xor_sync(0xffffffffu, s, 1);
    float nm  = fmaxf(m, m_o);
    float es  = __expf(m - nm);
    float eo  = __expf(m_o - nm);
    float denom = s * es + s_o * eo;
    float inv = 1.f / denom;

    float* outp = sa + ((size_t)(b * NQ_ + q)) * C_ + h * 32;
    #pragma unroll
    for (int d = 0; d < 32; d++) {
        float t = acc[d] * es + __shfl_xor_sync(0xffffffffu, acc[d], 1) * eo;
        if (q < NQ_ && (d >> 4) == hf) outp[d] = t * inv;
    }
}

// ---------------- Deformable sampling (warp per head, lane = channel) -------
__global__ void __launch_bounds__(256) deform_kernel(
    const float* __restrict__ v, const float* __restrict__ offb,
    const float* __restrict__ awb, const float* __restrict__ refp,
    float* __restrict__ ca)
{
    int bq = blockIdx.x;
    int h = threadIdx.x >> 5;
    int lane = threadIdx.x & 31;

    float lg = (lane < 12) ? awb[(size_t)bq * 96 + h * 12 + lane] : -INFINITY;
    float mx = lg;
    #pragma unroll
    for (int o = 16; o; o >>= 1) mx = fmaxf(mx, __shfl_xor_sync(0xffffffffu, mx, o));
    float e = (lane < 12) ? __expf(lg - mx) : 0.f;
    float ssum = e;
    #pragma unroll
    for (int o = 16; o; o >>= 1) ssum += __shfl_xor_sync(0xffffffffu, ssum, o);
    float myaw = e / ssum;

    const int Wl[3] = {128, 64, 32};
    const int Hl[3] = {128, 64, 32};
    const int st[3] = {0, 16384, 20480};

    float acc = 0.f;
    const float* offrow = offb + (size_t)bq * 192 + h * 24;
    const float* refrow = refp + (size_t)bq * 6;
    int bbase = (bq / NQ_) * LEN_IN_;

    #pragma unroll
    for (int l = 0; l < 3; l++) {
        float Wf = (float)Wl[l], Hf = (float)Hl[l];
        float rx = refrow[l * 2 + 0];
        float ry = refrow[l * 2 + 1];
        #pragma unroll
        for (int p = 0; p < 4; p++) {
            float ox = offrow[(l * 4 + p) * 2 + 0];
            float oy = offrow[(l * 4 + p) * 2 + 1];
            float lx = rx + ox / Wf;
            float ly = ry + oy / Hf;
            float x = lx * Wf - 0.5f;
            float y = ly * Hf - 0.5f;
            float x0 = floorf(x), y0 = floorf(y);
            float fx = x - x0, fy = y - y0;
            int ix = (int)x0, iy = (int)y0;
            float a = __shfl_sync(0xffffffffu, myaw, l * 4 + p);
            #pragma unroll
            for (int dy = 0; dy < 2; dy++) {
                int yi = iy + dy;
                if (yi < 0 || yi >= Hl[l]) continue;
                float wy = dy ? fy : (1.f - fy);
                #pragma unroll
                for (int dx = 0; dx < 2; dx++) {
                    int xi = ix + dx;
                    if (xi < 0 || xi >= Wl[l]) continue;
                    float w = wy * (dx ? fx : (1.f - fx));
                    int pos = st[l] + yi * Wl[l] + xi;
                    acc += a * w * v[((size_t)(bbase + pos) * H_ + h) * DH_ + lane];
                }
            }
        }
    }
    ca[(size_t)bq * C_ + h * DH_ + lane] = acc;
}

// ---------------------------------------------------------------------------
extern "C" void kernel_launch(void* const* d_in, const int* in_sizes, int n_in,
                              void* d_out, int out_size)
{
    const float* tgt        = (const float*)d_in[0];
    const float* memory     = (const float*)d_in[1];
    const float* query_pos  = (const float*)d_in[3];
    const float* qref       = (const float*)d_in[5];
    const unsigned char* kpm = (const unsigned char*)d_in[7];
    const float* ln1g = (const float*)d_in[9];
    const float* ln1b = (const float*)d_in[10];
    const float* ln2g = (const float*)d_in[11];
    const float* ln2b = (const float*)d_in[12];
    const float* ln3g = (const float*)d_in[13];
    const float* ln3b = (const float*)d_in[14];
    const float* attn_in_w  = (const float*)d_in[15];
    const float* attn_in_b  = (const float*)d_in[16];
    const float* attn_out_w = (const float*)d_in[17];
    const float* attn_out_b = (const float*)d_in[18];
    const float* off_w  = (const float*)d_in[19];
    const float* off_b  = (const float*)d_in[20];
    const float* aw_w   = (const float*)d_in[21];
    const float* aw_b   = (const float*)d_in[22];
    const float* vproj_w = (const float*)d_in[23];
    const float* vproj_b = (const float*)d_in[24];
    const float* oproj_w = (const float*)d_in[25];
    const float* oproj_b = (const float*)d_in[26];
    const float* ffn1_w = (const float*)d_in[27];
    const float* ffn1_b = (const float*)d_in[28];
    const float* ffn2_w = (const float*)d_in[29];
    const float* ffn2_b = (const float*)d_in[30];
    float* out = (float*)d_out;

    float *p_t2, *p_qk, *p_qkv, *p_sa, *p_tgt1, *p_tgt2, *p_v, *p_off, *p_aw, *p_ca;
    __half *p_t2h, *p_hidh, *p_wvh, *p_w1h, *p_w2h;
    cudaGetSymbolAddress((void**)&p_t2,   g_t2);
    cudaGetSymbolAddress((void**)&p_qk,   g_qk);
    cudaGetSymbolAddress((void**)&p_qkv,  g_qkv);
    cudaGetSymbolAddress((void**)&p_sa,   g_sa);
    cudaGetSymbolAddress((void**)&p_tgt1, g_tgt1);
    cudaGetSymbolAddress((void**)&p_tgt2, g_tgt2);
    cudaGetSymbolAddress((void**)&p_v,    g_v);
    cudaGetSymbolAddress((void**)&p_off,  g_off);
    cudaGetSymbolAddress((void**)&p_aw,   g_aw);
    cudaGetSymbolAddress((void**)&p_ca,   g_ca);
    cudaGetSymbolAddress((void**)&p_t2h,  g_t2h);
    cudaGetSymbolAddress((void**)&p_hidh, g_hidh);
    cudaGetSymbolAddress((void**)&p_wvh,  g_wvh);
    cudaGetSymbolAddress((void**)&p_w1h,  g_w1h);
    cudaGetSymbolAddress((void**)&p_w2h,  g_w2h);

    int attn_smem = NQ_ * DH_ * 2 * sizeof(float);   // 76800
    cudaFuncSetAttribute(attn_kernel, cudaFuncAttributeMaxDynamicSharedMemorySize, attn_smem);

    dim3 blk(256);
    const int MT_TILES = (MTGT + 127) / 128;   // 38
    const int MV_TILES = MV / 128;             // 2688

    // 0) weight fp16 conversions (cheap; graph-capturable)
    cvt_kernel<<<(C_*C_/4 + 255)/256, blk>>>(vproj_w, p_wvh, C_*C_);
    cvt_kernel<<<(DFF_*C_/4 + 255)/256, blk>>>(ffn1_w, p_w1h, DFF_*C_);
    cvt_kernel<<<(C_*DFF_/4 + 255)/256, blk>>>(ffn2_w, p_w2h, C_*DFF_);

    // 1) LN1 -> t2, qk = t2 + query_pos
    ln_kernel<<<MTGT, blk>>>(tgt, ln1g, ln1b, query_pos, p_t2, p_qk, nullptr);

    // 2) Q,K = qk @ Wqk^T ; V = t2 @ Wv^T  (into qkv[.,768])
    gemm_mma<<<dim3(8, MT_TILES), blk>>>(p_qk, attn_in_w, attn_in_b,
        nullptr, p_qkv, MTGT, 512, C_, 768, 0, 0);
    gemm_mma<<<dim3(4, MT_TILES), blk>>>(p_t2, attn_in_w + 512*C_, attn_in_b + 512,
        nullptr, p_qkv, MTGT, 256, C_, 768, 512, 0);

    // 3) self-attention -> sa  (2 threads per q, 128 q per block)
    attn_kernel<<<dim3(B_ * H_, 3), blk, attn_smem>>>(p_qkv, p_sa);

    // 4) tgt1 = tgt + sa @ attn_out_w^T + b
    gemm_mma<<<dim3(4, MT_TILES), blk>>>(p_sa, attn_out_w, attn_out_b,
        tgt, p_tgt1, MTGT, C_, C_, C_, 0, 2);

    // 5) LN2 -> t2 (fp32, feeds off/aw GEMMs)
    ln_kernel<<<MTGT, blk>>>(p_tgt1, ln2g, ln2b, nullptr, p_t2, nullptr, nullptr);

    // 6) v = memory @ vproj^T + b, masked  (dominant GEMM, fp16 v2)
    gemm_f16v<false,false><<<dim3(4, MV_TILES), blk>>>(memory, p_wvh, vproj_b,
        nullptr, kpm, p_v, MV, C_, C_, 3);

    // 7) offsets and attention-weight logits
    gemm_mma<<<dim3(3, MT_TILES), blk>>>(p_t2, off_w, off_b,
        nullptr, p_off, MTGT, 192, C_, 192, 0, 0);
    gemm_mma<<<dim3(2, MT_TILES), blk>>>(p_t2, aw_w, aw_b,
        nullptr, p_aw, MTGT, 96, C_, 96, 0, 0);

    // 8) deformable sampling (softmax fused) -> ca
    deform_kernel<<<MTGT, blk>>>(p_v, p_off, p_aw, qref, p_ca);

    // 9) tgt2 = tgt1 + ca @ oproj^T + b
    gemm_mma<<<dim3(4, MT_TILES), blk>>>(p_ca, oproj_w, oproj_b,
        p_tgt1, p_tgt2, MTGT, C_, C_, C_, 0, 2);

    // 10) LN3 -> t2h (fp16 only; feeds ffn1)
    ln_kernel<<<MTGT, blk>>>(p_tgt2, ln3g, ln3b, nullptr, nullptr, nullptr, p_t2h);

    // 11) FFN: hidh = relu(t2h @ w1h^T + b) in fp16; out = tgt2 + hidh @ w2h^T + b
    gemm_f16v<true,true><<<dim3(DFF_/64, MT_TILES), blk>>>(p_t2h, p_w1h, ffn1_b,
        nullptr, nullptr, p_hidh, MTGT, DFF_, C_, 1);
    gemm_f16v<true,false><<<dim3(4, MT_TILES), blk>>>(p_hidh, p_w2h, ffn2_b,
        p_tgt2, nullptr, out, MTGT, C_, DFF_, 2);
}

// round 10
// speedup vs baseline: 1.8856x; 1.8856x over previous
#include <cuda_runtime.h>
#include <cuda_bf16.h>
#include <cuda_fp16.h>
#include <math.h>

#define B_   16
#define NQ_  300
#define C_   256
#define H_   8
#define DH_  32
#define L_   3
#define P_   4
#define DFF_ 2048
#define LEN_IN_ 21504
#define MTGT (B_*NQ_)      // 4800
#define MV   (B_*LEN_IN_)  // 344064

// ---------------- scratch (device globals; no allocation allowed) ----------
__device__ float g_t2  [MTGT*C_];
__device__ float g_qk  [MTGT*C_];
__device__ float g_qkv [MTGT*3*C_];
__device__ float g_sa  [MTGT*C_];
__device__ float g_tgt1[MTGT*C_];
__device__ float g_tgt2[MTGT*C_];
__device__ float g_v   [(size_t)MV*C_];
__device__ float g_off [MTGT*H_*L_*P_*2];
__device__ float g_aw  [MTGT*H_*L_*P_];
__device__ float g_ca  [MTGT*C_];
__device__ __half g_t2h [MTGT*C_];
__device__ __half g_hidh[MTGT*DFF_];
__device__ __half g_wvh [C_*C_];
__device__ __half g_w1h [DFF_*C_];
__device__ __half g_w2h [C_*DFF_];

// ---------------- fp32 -> fp16 convert (weights) ---------------------------
__global__ void __launch_bounds__(256) cvt_kernel(
    const float* __restrict__ x, __half* __restrict__ y, int n)
{
    int i = (blockIdx.x * 256 + threadIdx.x) * 4;
    if (i < n) {
        float4 v = *(const float4*)(x + i);
        __half2 lo = __floats2half2_rn(v.x, v.y);
        __half2 hi = __floats2half2_rn(v.z, v.w);
        uint2 o; o.x = *(unsigned*)&lo; o.y = *(unsigned*)&hi;
        *(uint2*)(y + i) = o;
    }
}

// ---------------- LayerNorm (+ optional pos add / fp16 out) ----------------
__global__ void __launch_bounds__(256) ln_kernel(
    const float* __restrict__ x, const float* __restrict__ g,
    const float* __restrict__ b, const float* __restrict__ pos,
    float* __restrict__ t2, float* __restrict__ qk, __half* __restrict__ t2h)
{
    int row = blockIdx.x;
    int tid = threadIdx.x;
    size_t idx = (size_t)row * C_ + tid;
    float v = x[idx];

    __shared__ float red[8];
    float s = v;
    #pragma unroll
    for (int o = 16; o; o >>= 1) s += __shfl_xor_sync(0xffffffffu, s, o);
    if ((tid & 31) == 0) red[tid >> 5] = s;
    __syncthreads();
    float tot = 0.f;
    #pragma unroll
    for (int i = 0; i < 8; i++) tot += red[i];
    float mu = tot * (1.f / 256.f);
    float d = v - mu;
    __syncthreads();
    float s2 = d * d;
    #pragma unroll
    for (int o = 16; o; o >>= 1) s2 += __shfl_xor_sync(0xffffffffu, s2, o);
    if ((tid & 31) == 0) red[tid >> 5] = s2;
    __syncthreads();
    float tot2 = 0.f;
    #pragma unroll
    for (int i = 0; i < 8; i++) tot2 += red[i];
    float var = tot2 * (1.f / 256.f);

    float y = d * rsqrtf(var + 1e-5f) * g[tid] + b[tid];
    if (t2)  t2[idx] = y;
    if (t2h) t2h[idx] = __float2half_rn(y);
    if (pos) qk[idx] = y + pos[idx];
}

// ======================= MMA helpers =======================================
__device__ __forceinline__ void mma_bf16(
    float& c0, float& c1, float& c2, float& c3,
    unsigned a0, unsigned a1, unsigned a2, unsigned a3,
    unsigned b0, unsigned b1)
{
    asm volatile(
        "mma.sync.aligned.m16n8k16.row.col.f32.bf16.bf16.f32 "
        "{%0,%1,%2,%3}, {%4,%5,%6,%7}, {%8,%9}, {%0,%1,%2,%3};"
        : "+f"(c0), "+f"(c1), "+f"(c2), "+f"(c3)
        : "r"(a0), "r"(a1), "r"(a2), "r"(a3), "r"(b0), "r"(b1));
}

__device__ __forceinline__ void mma_f16(
    float& c0, float& c1, float& c2, float& c3,
    unsigned a0, unsigned a1, unsigned a2, unsigned a3,
    unsigned b0, unsigned b1)
{
    asm volatile(
        "mma.sync.aligned.m16n8k16.row.col.f32.f16.f16.f32 "
        "{%0,%1,%2,%3}, {%4,%5,%6,%7}, {%8,%9}, {%0,%1,%2,%3};"
        : "+f"(c0), "+f"(c1), "+f"(c2), "+f"(c3)
        : "r"(a0), "r"(a1), "r"(a2), "r"(a3), "r"(b0), "r"(b1));
}

__device__ __forceinline__ void split2(float e0, float e1,
                                       unsigned& hi, unsigned& lo)
{
    __nv_bfloat16 h0 = __float2bfloat16_rn(e0);
    __nv_bfloat16 h1 = __float2bfloat16_rn(e1);
    float r0 = e0 - __bfloat162float(h0);
    float r1 = e1 - __bfloat162float(h1);
    __nv_bfloat162 hp; hp.x = h0; hp.y = h1;
    __nv_bfloat162 lp = __floats2bfloat162_rn(r0, r1);
    hi = *(unsigned*)&hp;
    lo = *(unsigned*)&lp;
}

__device__ __forceinline__ unsigned pack_h2(float e0, float e1)
{
    __half2 h = __floats2half2_rn(e0, e1);
    return *(unsigned*)&h;
}

// ======================= bf16x3 tensor-core GEMM ===========================
// C[M,N] = A[M,K] @ W[N,K]^T + bias. Tile 128x64x16, 8 warps, warp 32x32.
// epi: 0=bias  1=bias+relu  2=bias+residual
__global__ void __launch_bounds__(256, 2) gemm_mma(
    const float* __restrict__ A, const float* __restrict__ W,
    const float* __restrict__ bias, const float* __restrict__ resid,
    float* __restrict__ Cc, int M, int N, int K, int ldc, int coloff, int epi)
{
    __shared__ __align__(16) unsigned AsH[8*32*4];
    __shared__ __align__(16) unsigned AsL[8*32*4];
    __shared__ __align__(16) unsigned BsH[4*32*2*2];
    __shared__ __align__(16) unsigned BsL[4*32*2*2];

    int tid = threadIdx.x;
    int wid = tid >> 5, lane = tid & 31;
    int wm = wid & 3, wn = wid >> 2;
    int row0 = blockIdx.y * 128;
    int col0 = blockIdx.x * 64;

    int arow = tid >> 1;
    int ak0  = (tid & 1) * 8;
    int brow = tid >> 2;
    int bk0  = (tid & 3) * 4;

    int grow = row0 + arow;
    int gcol = col0 + brow;
    bool avalid = grow < M;
    bool bvalid = gcol < N;
    const float* Aptr = A + (size_t)grow * K + ak0;
    const float* Wptr = W + (size_t)gcol * K + bk0;

    int a_mt = arow >> 4;
    int a_g  = arow & 15;
    int a_laneg = a_g & 7;
    int a_regrow = a_g >> 3;
    int b_nt  = brow >> 3;
    int b_g   = brow & 7;
    int b_pair = b_nt >> 1;
    int b_sub  = b_nt & 1;

    float acc[2][4][4];
    #pragma unroll
    for (int i = 0; i < 2; i++)
        #pragma unroll
        for (int j = 0; j < 4; j++)
            #pragma unroll
            for (int r = 0; r < 4; r++) acc[i][j][r] = 0.f;

    float4 zf4 = make_float4(0.f, 0.f, 0.f, 0.f);
    float4 aR0 = avalid ? *(const float4*)(Aptr)     : zf4;
    float4 aR1 = avalid ? *(const float4*)(Aptr + 4) : zf4;
    float4 bR0 = bvalid ? *(const float4*)(Wptr)     : zf4;

    for (int kt = 0; kt < K; kt += 16) {
        {
            int reg = a_regrow + 2 * (ak0 >> 3);
            int t4  = (ak0 & 7) >> 1;
            unsigned hi, lo;
            int base = (a_mt * 32 + a_laneg * 4 + t4) * 4 + reg;
            split2(aR0.x, aR0.y, hi, lo); AsH[base] = hi; AsL[base] = lo;
            base = (a_mt * 32 + a_laneg * 4 + t4 + 1) * 4 + reg;
            split2(aR0.z, aR0.w, hi, lo); AsH[base] = hi; AsL[base] = lo;
            int ak1 = ak0 + 4;
            reg = a_regrow + 2 * (ak1 >> 3);
            t4  = (ak1 & 7) >> 1;
            base = (a_mt * 32 + a_laneg * 4 + t4) * 4 + reg;
            split2(aR1.x, aR1.y, hi, lo); AsH[base] = hi; AsL[base] = lo;
            base = (a_mt * 32 + a_laneg * 4 + t4 + 1) * 4 + reg;
            split2(aR1.z, aR1.w, hi, lo); AsH[base] = hi; AsL[base] = lo;
            int breg = bk0 >> 3;
            int bt4  = (bk0 & 7) >> 1;
            base = ((b_pair * 32 + b_g * 4 + bt4) * 2 + b_sub) * 2 + breg;
            split2(bR0.x, bR0.y, hi, lo); BsH[base] = hi; BsL[base] = lo;
            base = ((b_pair * 32 + b_g * 4 + bt4 + 1) * 2 + b_sub) * 2 + breg;
            split2(bR0.z, bR0.w, hi, lo); BsH[base] = hi; BsL[base] = lo;
        }
        __syncthreads();

        if (kt + 16 < K) {
            aR0 = avalid ? *(const float4*)(Aptr + kt + 16)     : zf4;
            aR1 = avalid ? *(const float4*)(Aptr + kt + 16 + 4) : zf4;
            bR0 = bvalid ? *(const float4*)(Wptr + kt + 16)     : zf4;
        }

        uint4 aH[2], aL[2], bH[2], bL[2];
        #pragma unroll
        for (int mt = 0; mt < 2; mt++) {
            int idx = ((wm * 2 + mt) * 32 + lane) * 4;
            aH[mt] = *(const uint4*)&AsH[idx];
            aL[mt] = *(const uint4*)&AsL[idx];
        }
        #pragma unroll
        for (int np = 0; np < 2; np++) {
            int idx = ((wn * 2 + np) * 32 + lane) * 4;
            bH[np] = *(const uint4*)&BsH[idx];
            bL[np] = *(const uint4*)&BsL[idx];
        }
        #pragma unroll
        for (int mt = 0; mt < 2; mt++) {
            #pragma unroll
            for (int nt = 0; nt < 4; nt++) {
                int np = nt >> 1, sub = nt & 1;
                unsigned bh0 = sub ? bH[np].z : bH[np].x;
                unsigned bh1 = sub ? bH[np].w : bH[np].y;
                unsigned bl0 = sub ? bL[np].z : bL[np].x;
                unsigned bl1 = sub ? bL[np].w : bL[np].y;
                float* c = acc[mt][nt];
                mma_bf16(c[0], c[1], c[2], c[3],
                         aH[mt].x, aH[mt].y, aH[mt].z, aH[mt].w, bh0, bh1);
                mma_bf16(c[0], c[1], c[2], c[3],
                         aH[mt].x, aH[mt].y, aH[mt].z, aH[mt].w, bl0, bl1);
                mma_bf16(c[0], c[1], c[2], c[3],
                         aL[mt].x, aL[mt].y, aL[mt].z, aL[mt].w, bh0, bh1);
            }
        }
        __syncthreads();
    }

    int g = lane >> 2, t4 = lane & 3;
    #pragma unroll
    for (int mt = 0; mt < 2; mt++) {
        #pragma unroll
        for (int nt = 0; nt < 4; nt++) {
            int r = row0 + wm * 32 + mt * 16 + g;
            int c = col0 + wn * 32 + nt * 8 + t4 * 2;
            if (c >= N) continue;
            float b0 = bias[c], b1 = bias[c + 1];
            #pragma unroll
            for (int half = 0; half < 2; half++) {
                int rr = r + half * 8;
                if (rr >= M) continue;
                float v0 = acc[mt][nt][half * 2 + 0] + b0;
                float v1 = acc[mt][nt][half * 2 + 1] + b1;
                if (epi == 1) { v0 = fmaxf(v0, 0.f); v1 = fmaxf(v1, 0.f); }
                else if (epi == 2) {
                    const float* rp = resid + (size_t)rr * ldc + coloff + c;
                    v0 += rp[0]; v1 += rp[1];
                }
                float2 o; o.x = v0; o.y = v1;
                *(float2*)(Cc + (size_t)rr * ldc + coloff + c) = o;
            }
        }
    }
}

// ======================= fp16x1 GEMM v3 ====================================
// v1 (stride-4, conflict-free) fragment layout; BK=16; fp16 weights direct.
// AH: A is fp16; OH: output fp16.  epi: 1=relu 2=residual 3=mask-zero
template<bool AH, bool OH>
__global__ void __launch_bounds__(256, 2) gemm_f16v(
    const void* __restrict__ Av, const __half* __restrict__ Wh,
    const float* __restrict__ bias, const float* __restrict__ resid,
    const unsigned char* __restrict__ mask,
    void* __restrict__ Cv, int M, int N, int K, int epi)
{
    __shared__ __align__(16) unsigned As[8*32*4];
    __shared__ __align__(16) unsigned Bs[4*32*2*2];

    int tid = threadIdx.x;
    int wid = tid >> 5, lane = tid & 31;
    int wm = wid & 3, wn = wid >> 2;
    int row0 = blockIdx.y * 128;
    int col0 = blockIdx.x * 64;

    // A staging: thread covers (arow, 8 k at ak0)
    int arow = tid >> 1;
    int ak0  = (tid & 1) * 8;
    int a_mt = arow >> 4;
    int a_g  = arow & 15;
    int a_laneg = a_g & 7;
    int a_regrow = a_g >> 3;
    int a_kreg = ak0 >> 3;           // 0 or 1 (k-octet)
    // B staging: thread covers (brow, 4 k at bk0)
    int brow = tid >> 2;
    int bk0  = (tid & 3) * 4;
    int b_nt = brow >> 3;
    int b_g  = brow & 7;
    int b_pair = b_nt >> 1;
    int b_sub  = b_nt & 1;
    int b_reg  = bk0 >> 3;
    int b_t4   = (bk0 & 7) >> 1;

    int grow = row0 + arow;
    int gcol = col0 + brow;
    bool avalid = grow < M;
    bool bvalid = gcol < N;

    const __half* Aph = AH ? ((const __half*)Av + (size_t)grow * K + ak0) : nullptr;
    const float*  Apf = AH ? nullptr : ((const float*)Av + (size_t)grow * K + ak0);
    const __half* Wp  = Wh + (size_t)gcol * K + bk0;

    float acc[2][4][4];
    #pragma unroll
    for (int i = 0; i < 2; i++)
        #pragma unroll
        for (int j = 0; j < 4; j++)
            #pragma unroll
            for (int r = 0; r < 4; r++) acc[i][j][r] = 0.f;

    float4 zf4 = make_float4(0.f, 0.f, 0.f, 0.f);
    uint4  zu4 = make_uint4(0, 0, 0, 0);
    uint2  zu2 = make_uint2(0, 0);

    uint4  aU;        // fp16 A: 8 halves
    float4 aR0, aR1;  // fp32 A: 8 floats
    uint2  bU;        // fp16 W: 4 halves

    if (AH) aU = avalid ? *(const uint4*)(Aph) : zu4;
    else {
        aR0 = avalid ? *(const float4*)(Apf)     : zf4;
        aR1 = avalid ? *(const float4*)(Apf + 4) : zf4;
    }
    bU = bvalid ? *(const uint2*)(Wp) : zu2;

    for (int kt = 0; kt < K; kt += 16) {
        // ---- store staged regs to fragment smem (v1 conflict-free layout)
        if (AH) {
            const unsigned* au = (const unsigned*)&aU;
            #pragma unroll
            for (int j = 0; j < 4; j++)
                As[(a_mt * 32 + a_laneg * 4 + j) * 4 + a_regrow + 2 * a_kreg] = au[j];
        } else {
            As[(a_mt * 32 + a_laneg * 4 + 0) * 4 + a_regrow + 2 * a_kreg] = pack_h2(aR0.x, aR0.y);
            As[(a_mt * 32 + a_laneg * 4 + 1) * 4 + a_regrow + 2 * a_kreg] = pack_h2(aR0.z, aR0.w);
            As[(a_mt * 32 + a_laneg * 4 + 2) * 4 + a_regrow + 2 * a_kreg] = pack_h2(aR1.x, aR1.y);
            As[(a_mt * 32 + a_laneg * 4 + 3) * 4 + a_regrow + 2 * a_kreg] = pack_h2(aR1.z, aR1.w);
        }
        Bs[((b_pair * 32 + b_g * 4 + b_t4)     * 2 + b_sub) * 2 + b_reg] = bU.x;
        Bs[((b_pair * 32 + b_g * 4 + b_t4 + 1) * 2 + b_sub) * 2 + b_reg] = bU.y;
        __syncthreads();

        // ---- prefetch next k-tile
        if (kt + 16 < K) {
            if (AH) aU = avalid ? *(const uint4*)(Aph + kt + 16) : zu4;
            else {
                aR0 = avalid ? *(const float4*)(Apf + kt + 16)     : zf4;
                aR1 = avalid ? *(const float4*)(Apf + kt + 16 + 4) : zf4;
            }
            bU = bvalid ? *(const uint2*)(Wp + kt + 16) : zu2;
        }

        // ---- consume fragments
        uint4 aF[2], bF[2];
        #pragma unroll
        for (int mt = 0; mt < 2; mt++)
            aF[mt] = *(const uint4*)&As[((wm * 2 + mt) * 32 + lane) * 4];
        #pragma unroll
        for (int np = 0; np < 2; np++)
            bF[np] = *(const uint4*)&Bs[((wn * 2 + np) * 32 + lane) * 4];

        #pragma unroll
        for (int mt = 0; mt < 2; mt++) {
            #pragma unroll
            for (int nt = 0; nt < 4; nt++) {
                int np = nt >> 1, sub = nt & 1;
                unsigned bh0 = sub ? bF[np].z : bF[np].x;
                unsigned bh1 = sub ? bF[np].w : bF[np].y;
                float* c = acc[mt][nt];
                mma_f16(c[0], c[1], c[2], c[3],
                        aF[mt].x, aF[mt].y, aF[mt].z, aF[mt].w, bh0, bh1);
            }
        }
        __syncthreads();
    }

    // ---- epilogue
    int g = lane >> 2, t4 = lane & 3;
    #pragma unroll
    for (int mt = 0; mt < 2; mt++) {
        #pragma unroll
        for (int nt = 0; nt < 4; nt++) {
            int r = row0 + wm * 32 + mt * 16 + g;
            int c = col0 + wn * 32 + nt * 8 + t4 * 2;
            if (c >= N) continue;
            float b0 = bias[c], b1 = bias[c + 1];
            #pragma unroll
            for (int half = 0; half < 2; half++) {
                int rr = r + half * 8;
                if (rr >= M) continue;
                float v0 = acc[mt][nt][half * 2 + 0] + b0;
                float v1 = acc[mt][nt][half * 2 + 1] + b1;
                if (epi == 1) { v0 = fmaxf(v0, 0.f); v1 = fmaxf(v1, 0.f); }
                else if (epi == 2) {
                    const float* rp = resid + (size_t)rr * N + c;
                    v0 += rp[0]; v1 += rp[1];
                }
                else if (epi == 3 && mask[rr]) { v0 = 0.f; v1 = 0.f; }
                if (OH) {
                    __half2 o = __floats2half2_rn(v0, v1);
                    *(__half2*)((__half*)Cv + (size_t)rr * N + c) = o;
                } else {
                    float2 o; o.x = v0; o.y = v1;
                    *(float2*)((float*)Cv + (size_t)rr * N + c) = o;
                }
            }
        }
    }
}

// ---------------- Self-attention (split-k flash: 2 threads per q) ----------
__global__ void __launch_bounds__(256) attn_kernel(
    const float* __restrict__ qkv, float* __restrict__ sa)
{
    int b = blockIdx.x / H_;
    int h = blockIdx.x % H_;
    int q0 = blockIdx.y * 128;
    extern __shared__ float sm[];
    float* Ks = sm;
    float* Vs = sm + NQ_ * DH_;
    int tid = threadIdx.x;

    for (int i = tid; i < NQ_ * DH_; i += 256) {
        int r = i >> 5, d = i & 31;
        const float* base = qkv + ((size_t)(b * NQ_ + r)) * 768 + h * 32 + d;
        Ks[i] = base[256];
        Vs[i] = base[512];
    }
    __syncthreads();

    int q  = q0 + (tid >> 1);
    int hf = tid & 1;

    float m = -1e30f, s = 0.f;
    float acc[32];
    #pragma unroll
    for (int d = 0; d < 32; d++) acc[d] = 0.f;

    if (q < NQ_) {
        float4 qv[8];
        const float4* qb = (const float4*)(qkv + ((size_t)(b * NQ_ + q)) * 768 + h * 32);
        #pragma unroll
        for (int u = 0; u < 8; u++) qv[u] = qb[u];

        int kbeg = hf * 150, kend = kbeg + 150;
        for (int k = kbeg; k < kend; k++) {
            const float4* kb = (const float4*)(Ks + k * 32);
            float dot = 0.f;
            #pragma unroll
            for (int u = 0; u < 8; u++) {
                float4 kv = kb[u];
                dot += qv[u].x * kv.x + qv[u].y * kv.y + qv[u].z * kv.z + qv[u].w * kv.w;
            }
            dot *= 0.17677669529663687f;   // 1/sqrt(32)
            float nm = fmaxf(m, dot);
            float corr = __expf(m - nm);
            float e = __expf(dot - nm);
            s = s * corr + e;
            const float4* vb = (const float4*)(Vs + k * 32);
            #pragma unroll
            for (int u = 0; u < 8; u++) {
                float4 vv = vb[u];
                acc[4*u+0] = acc[4*u+0] * corr + e * vv.x;
                acc[4*u+1] = acc[4*u+1] * corr + e * vv.y;
                acc[4*u+2] = acc[4*u+2] * corr + e * vv.z;
                acc[4*u+3] = acc[4*u+3] * corr + e * vv.w;
            }
            m = nm;
        }
    }

    // merge partner halves (lanes differ by 1)
    float m_o = __shfl_xor_sync(0xffffffffu, m, 1);
    float s_o = __shfl_xor_sync(0xffffffffu, s, 1);
    float nm  = fmaxf(m, m_o);
    float es  = __expf(m - nm);
    float eo  = __expf(m_o - nm);
    float denom = s * es + s_o * eo;
    float inv = 1.f / denom;

    float* outp = sa + ((size_t)(b * NQ_ + q)) * C_ + h * 32;
    #pragma unroll
    for (int d = 0; d < 32; d++) {
        float t = acc[d] * es + __shfl_xor_sync(0xffffffffu, acc[d], 1) * eo;
        if (q < NQ_ && (d >> 4) == hf) outp[d] = t * inv;
    }
}

// ---------------- Deformable sampling (warp per head, lane = channel) -------
__global__ void __launch_bounds__(256) deform_kernel(
    const float* __restrict__ v, const float* __restrict__ offb,
    const float* __restrict__ awb, const float* __restrict__ refp,
    float* __restrict__ ca)
{
    int bq = blockIdx.x;
    int h = threadIdx.x >> 5;
    int lane = threadIdx.x & 31;

    float lg = (lane < 12) ? awb[(size_t)bq * 96 + h * 12 + lane] : -INFINITY;
    float mx = lg;
    #pragma unroll
    for (int o = 16; o; o >>= 1) mx = fmaxf(mx, __shfl_xor_sync(0xffffffffu, mx, o));
    float e = (lane < 12) ? __expf(lg - mx) : 0.f;
    float ssum = e;
    #pragma unroll
    for (int o = 16; o; o >>= 1) ssum += __shfl_xor_sync(0xffffffffu, ssum, o);
    float myaw = e / ssum;

    const int Wl[3] = {128, 64, 32};
    const int Hl[3] = {128, 64, 32};
    const int st[3] = {0, 16384, 20480};

    float acc = 0.f;
    const float* offrow = offb + (size_t)bq * 192 + h * 24;
    const float* refrow = refp + (size_t)bq * 6;
    int bbase = (bq / NQ_) * LEN_IN_;

    #pragma unroll
    for (int l = 0; l < 3; l++) {
        float Wf = (float)Wl[l], Hf = (float)Hl[l];
        float rx = refrow[l * 2 + 0];
        float ry = refrow[l * 2 + 1];
        #pragma unroll
        for (int p = 0; p < 4; p++) {
            float ox = offrow[(l * 4 + p) * 2 + 0];
            float oy = offrow[(l * 4 + p) * 2 + 1];
            float lx = rx + ox / Wf;
            float ly = ry + oy / Hf;
            float x = lx * Wf - 0.5f;
            float y = ly * Hf - 0.5f;
            float x0 = floorf(x), y0 = floorf(y);
            float fx = x - x0, fy = y - y0;
            int ix = (int)x0, iy = (int)y0;
            float a = __shfl_sync(0xffffffffu, myaw, l * 4 + p);
            #pragma unroll
            for (int dy = 0; dy < 2; dy++) {
                int yi = iy + dy;
                if (yi < 0 || yi >= Hl[l]) continue;
                float wy = dy ? fy : (1.f - fy);
                #pragma unroll
                for (int dx = 0; dx < 2; dx++) {
                    int xi = ix + dx;
                    if (xi < 0 || xi >= Wl[l]) continue;
                    float w = wy * (dx ? fx : (1.f - fx));
                    int pos = st[l] + yi * Wl[l] + xi;
                    acc += a * w * v[((size_t)(bbase + pos) * H_ + h) * DH_ + lane];
                }
            }
        }
    }
    ca[(size_t)bq * C_ + h * DH_ + lane] = acc;
}

// ---------------------------------------------------------------------------
extern "C" void kernel_launch(void* const* d_in, const int* in_sizes, int n_in,
                              void* d_out, int out_size)
{
    const float* tgt        = (const float*)d_in[0];
    const float* memory     = (const float*)d_in[1];
    const float* query_pos  = (const float*)d_in[3];
    const float* qref       = (const float*)d_in[5];
    const unsigned char* kpm = (const unsigned char*)d_in[7];
    const float* ln1g = (const float*)d_in[9];
    const float* ln1b = (const float*)d_in[10];
    const float* ln2g = (const float*)d_in[11];
    const float* ln2b = (const float*)d_in[12];
    const float* ln3g = (const float*)d_in[13];
    const float* ln3b = (const float*)d_in[14];
    const float* attn_in_w  = (const float*)d_in[15];
    const float* attn_in_b  = (const float*)d_in[16];
    const float* attn_out_w = (const float*)d_in[17];
    const float* attn_out_b = (const float*)d_in[18];
    const float* off_w  = (const float*)d_in[19];
    const float* off_b  = (const float*)d_in[20];
    const float* aw_w   = (const float*)d_in[21];
    const float* aw_b   = (const float*)d_in[22];
    const float* vproj_w = (const float*)d_in[23];
    const float* vproj_b = (const float*)d_in[24];
    const float* oproj_w = (const float*)d_in[25];
    const float* oproj_b = (const float*)d_in[26];
    const float* ffn1_w = (const float*)d_in[27];
    const float* ffn1_b = (const float*)d_in[28];
    const float* ffn2_w = (const float*)d_in[29];
    const float* ffn2_b = (const float*)d_in[30];
    float* out = (float*)d_out;

    float *p_t2, *p_qk, *p_qkv, *p_sa, *p_tgt1, *p_tgt2, *p_v, *p_off, *p_aw, *p_ca;
    __half *p_t2h, *p_hidh, *p_wvh, *p_w1h, *p_w2h;
    cudaGetSymbolAddress((void**)&p_t2,   g_t2);
    cudaGetSymbolAddress((void**)&p_qk,   g_qk);
    cudaGetSymbolAddress((void**)&p_qkv,  g_qkv);
    cudaGetSymbolAddress((void**)&p_sa,   g_sa);
    cudaGetSymbolAddress((void**)&p_tgt1, g_tgt1);
    cudaGetSymbolAddress((void**)&p_tgt2, g_tgt2);
    cudaGetSymbolAddress((void**)&p_v,    g_v);
    cudaGetSymbolAddress((void**)&p_off,  g_off);
    cudaGetSymbolAddress((void**)&p_aw,   g_aw);
    cudaGetSymbolAddress((void**)&p_ca,   g_ca);
    cudaGetSymbolAddress((void**)&p_t2h,  g_t2h);
    cudaGetSymbolAddress((void**)&p_hidh, g_hidh);
    cudaGetSymbolAddress((void**)&p_wvh,  g_wvh);
    cudaGetSymbolAddress((void**)&p_w1h,  g_w1h);
    cudaGetSymbolAddress((void**)&p_w2h,  g_w2h);

    int attn_smem = NQ_ * DH_ * 2 * sizeof(float);   // 76800
    cudaFuncSetAttribute(attn_kernel, cudaFuncAttributeMaxDynamicSharedMemorySize, attn_smem);

    dim3 blk(256);
    const int MT_TILES = (MTGT + 127) / 128;   // 38
    const int MV_TILES = MV / 128;             // 2688

    // 0) weight fp16 conversions (cheap; graph-capturable)
    cvt_kernel<<<(C_*C_/4 + 255)/256, blk>>>(vproj_w, p_wvh, C_*C_);
    cvt_kernel<<<(DFF_*C_/4 + 255)/256, blk>>>(ffn1_w, p_w1h, DFF_*C_);
    cvt_kernel<<<(C_*DFF_/4 + 255)/256, blk>>>(ffn2_w, p_w2h, C_*DFF_);

    // 1) LN1 -> t2, qk = t2 + query_pos
    ln_kernel<<<MTGT, blk>>>(tgt, ln1g, ln1b, query_pos, p_t2, p_qk, nullptr);

    // 2) Q,K = qk @ Wqk^T ; V = t2 @ Wv^T  (into qkv[.,768])
    gemm_mma<<<dim3(8, MT_TILES), blk>>>(p_qk, attn_in_w, attn_in_b,
        nullptr, p_qkv, MTGT, 512, C_, 768, 0, 0);
    gemm_mma<<<dim3(4, MT_TILES), blk>>>(p_t2, attn_in_w + 512*C_, attn_in_b + 512,
        nullptr, p_qkv, MTGT, 256, C_, 768, 512, 0);

    // 3) self-attention -> sa  (2 threads per q, 128 q per block)
    attn_kernel<<<dim3(B_ * H_, 3), blk, attn_smem>>>(p_qkv, p_sa);

    // 4) tgt1 = tgt + sa @ attn_out_w^T + b
    gemm_mma<<<dim3(4, MT_TILES), blk>>>(p_sa, attn_out_w, attn_out_b,
        tgt, p_tgt1, MTGT, C_, C_, C_, 0, 2);

    // 5) LN2 -> t2 (fp32, feeds off/aw GEMMs)
    ln_kernel<<<MTGT, blk>>>(p_tgt1, ln2g, ln2b, nullptr, p_t2, nullptr, nullptr);

    // 6) v = memory @ vproj^T + b, masked  (dominant GEMM, fp16 weights)
    gemm_f16v<false,false><<<dim3(4, MV_TILES), blk>>>(memory, p_wvh, vproj_b,
        nullptr, kpm, p_v, MV, C_, C_, 3);

    // 7) offsets and attention-weight logits
    gemm_mma<<<dim3(3, MT_TILES), blk>>>(p_t2, off_w, off_b,
        nullptr, p_off, MTGT, 192, C_, 192, 0, 0);
    gemm_mma<<<dim3(2, MT_TILES), blk>>>(p_t2, aw_w, aw_b,
        nullptr, p_aw, MTGT, 96, C_, 96, 0, 0);

    // 8) deformable sampling (softmax fused) -> ca
    deform_kernel<<<MTGT, blk>>>(p_v, p_off, p_aw, qref, p_ca);

    // 9) tgt2 = tgt1 + ca @ oproj^T + b
    gemm_mma<<<dim3(4, MT_TILES), blk>>>(p_ca, oproj_w, oproj_b,
        p_tgt1, p_tgt2, MTGT, C_, C_, C_, 0, 2);

    // 10) LN3 -> t2h (fp16 only; feeds ffn1)
    ln_kernel<<<MTGT, blk>>>(p_tgt2, ln3g, ln3b, nullptr, nullptr, nullptr, p_t2h);

    // 11) FFN: hidh = relu(t2h @ w1h^T + b) in fp16; out = tgt2 + hidh @ w2h^T + b
    gemm_f16v<true,true><<<dim3(DFF_/64, MT_TILES), blk>>>(p_t2h, p_w1h, ffn1_b,
        nullptr, nullptr, p_hidh, MTGT, DFF_, C_, 1);
    gemm_f16v<true,false><<<dim3(4, MT_TILES), blk>>>(p_hidh, p_w2h, ffn2_b,
        p_tgt2, nullptr, out, MTGT, C_, DFF_, 2);
}

// round 12
// speedup vs baseline: 1.9187x; 1.0176x over previous
#include <cuda_runtime.h>
#include <cuda_bf16.h>
#include <cuda_fp16.h>
#include <math.h>

#define B_   16
#define NQ_  300
#define C_   256
#define H_   8
#define DH_  32
#define L_   3
#define P_   4
#define DFF_ 2048
#define LEN_IN_ 21504
#define MTGT (B_*NQ_)      // 4800
#define MV   (B_*LEN_IN_)  // 344064

// ---------------- scratch (device globals; no allocation allowed) ----------
__device__ float  g_qkv [MTGT*3*C_];
__device__ float  g_sa  [MTGT*C_];
__device__ float  g_tgt1[MTGT*C_];
__device__ float  g_tgt2[MTGT*C_];
__device__ float  g_off [MTGT*H_*L_*P_*2];
__device__ float  g_aw  [MTGT*H_*L_*P_];
__device__ __half g_vh  [(size_t)MV*C_];
__device__ __half g_cah [MTGT*C_];
__device__ __half g_t2h [MTGT*C_];
__device__ __half g_qkh [MTGT*C_];
__device__ __half g_hidh[MTGT*DFF_];
__device__ __half g_wqkvh[3*C_*C_];
__device__ __half g_wouth[C_*C_];
__device__ __half g_woffh[192*C_];
__device__ __half g_wawh [96*C_];
__device__ __half g_woh  [C_*C_];
__device__ __half g_wvh  [C_*C_];
__device__ __half g_w1h  [DFF_*C_];
__device__ __half g_w2h  [C_*DFF_];

// ---------------- fp32 -> fp16 convert ------------------------------------
__global__ void __launch_bounds__(256) cvt_kernel(
    const float* __restrict__ x, __half* __restrict__ y, int n)
{
    int i = (blockIdx.x * 256 + threadIdx.x) * 4;
    if (i < n) {
        float4 v = *(const float4*)(x + i);
        __half2 lo = __floats2half2_rn(v.x, v.y);
        __half2 hi = __floats2half2_rn(v.z, v.w);
        uint2 o; o.x = *(unsigned*)&lo; o.y = *(unsigned*)&hi;
        *(uint2*)(y + i) = o;
    }
}

// ---------------- LayerNorm -> fp16 outputs (t2h, optional qk=t2+pos) ------
__global__ void __launch_bounds__(256) ln_kernel(
    const float* __restrict__ x, const float* __restrict__ g,
    const float* __restrict__ b, const float* __restrict__ pos,
    __half* __restrict__ t2h, __half* __restrict__ qkh)
{
    int row = blockIdx.x;
    int tid = threadIdx.x;
    size_t idx = (size_t)row * C_ + tid;
    float v = x[idx];

    __shared__ float red[8];
    float s = v;
    #pragma unroll
    for (int o = 16; o; o >>= 1) s += __shfl_xor_sync(0xffffffffu, s, o);
    if ((tid & 31) == 0) red[tid >> 5] = s;
    __syncthreads();
    float tot = 0.f;
    #pragma unroll
    for (int i = 0; i < 8; i++) tot += red[i];
    float mu = tot * (1.f / 256.f);
    float d = v - mu;
    __syncthreads();
    float s2 = d * d;
    #pragma unroll
    for (int o = 16; o; o >>= 1) s2 += __shfl_xor_sync(0xffffffffu, s2, o);
    if ((tid & 31) == 0) red[tid >> 5] = s2;
    __syncthreads();
    float tot2 = 0.f;
    #pragma unroll
    for (int i = 0; i < 8; i++) tot2 += red[i];
    float var = tot2 * (1.f / 256.f);

    float y = d * rsqrtf(var + 1e-5f) * g[tid] + b[tid];
    if (t2h) t2h[idx] = __float2half_rn(y);
    if (qkh) qkh[idx] = __float2half_rn(y + pos[idx]);
}

// ======================= MMA helper ========================================
__device__ __forceinline__ void mma_f16(
    float& c0, float& c1, float& c2, float& c3,
    unsigned a0, unsigned a1, unsigned a2, unsigned a3,
    unsigned b0, unsigned b1)
{
    asm volatile(
        "mma.sync.aligned.m16n8k16.row.col.f32.f16.f16.f32 "
        "{%0,%1,%2,%3}, {%4,%5,%6,%7}, {%8,%9}, {%0,%1,%2,%3};"
        : "+f"(c0), "+f"(c1), "+f"(c2), "+f"(c3)
        : "r"(a0), "r"(a1), "r"(a2), "r"(a3), "r"(b0), "r"(b1));
}

__device__ __forceinline__ unsigned pack_h2(float e0, float e1)
{
    __half2 h = __floats2half2_rn(e0, e1);
    return *(unsigned*)&h;
}

// ======================= fp16x1 GEMM (v3 layout) ===========================
// C[M,N](+coloff, stride ldc) = A[M,K] @ W[N,K]^T + bias
// Tile 128x64x16, 8 warps, conflict-free stride-4 fragment smem.
// AH: A fp16; OH: C fp16.  epi: 0=bias 1=relu 2=residual 3=mask-zero
template<bool AH, bool OH>
__global__ void __launch_bounds__(256, 2) gemm_f16v(
    const void* __restrict__ Av, const __half* __restrict__ Wh,
    const float* __restrict__ bias, const float* __restrict__ resid,
    const unsigned char* __restrict__ mask,
    void* __restrict__ Cv, int M, int N, int K, int ldc, int coloff, int epi)
{
    __shared__ __align__(16) unsigned As[8*32*4];
    __shared__ __align__(16) unsigned Bs[4*32*2*2];

    int tid = threadIdx.x;
    int wid = tid >> 5, lane = tid & 31;
    int wm = wid & 3, wn = wid >> 2;
    int row0 = blockIdx.y * 128;
    int col0 = blockIdx.x * 64;

    int arow = tid >> 1;
    int ak0  = (tid & 1) * 8;
    int a_mt = arow >> 4;
    int a_g  = arow & 15;
    int a_laneg = a_g & 7;
    int a_regrow = a_g >> 3;
    int a_kreg = ak0 >> 3;
    int brow = tid >> 2;
    int bk0  = (tid & 3) * 4;
    int b_nt = brow >> 3;
    int b_g  = brow & 7;
    int b_pair = b_nt >> 1;
    int b_sub  = b_nt & 1;
    int b_reg  = bk0 >> 3;
    int b_t4   = (bk0 & 7) >> 1;

    int grow = row0 + arow;
    int gcol = col0 + brow;
    bool avalid = grow < M;
    bool bvalid = gcol < N;

    const __half* Aph = AH ? ((const __half*)Av + (size_t)grow * K + ak0) : nullptr;
    const float*  Apf = AH ? nullptr : ((const float*)Av + (size_t)grow * K + ak0);
    const __half* Wp  = Wh + (size_t)gcol * K + bk0;

    float acc[2][4][4];
    #pragma unroll
    for (int i = 0; i < 2; i++)
        #pragma unroll
        for (int j = 0; j < 4; j++)
            #pragma unroll
            for (int r = 0; r < 4; r++) acc[i][j][r] = 0.f;

    float4 zf4 = make_float4(0.f, 0.f, 0.f, 0.f);
    uint4  zu4 = make_uint4(0, 0, 0, 0);
    uint2  zu2 = make_uint2(0, 0);

    uint4  aU;
    float4 aR0, aR1;
    uint2  bU;

    if (AH) aU = avalid ? *(const uint4*)(Aph) : zu4;
    else {
        aR0 = avalid ? *(const float4*)(Apf)     : zf4;
        aR1 = avalid ? *(const float4*)(Apf + 4) : zf4;
    }
    bU = bvalid ? *(const uint2*)(Wp) : zu2;

    for (int kt = 0; kt < K; kt += 16) {
        if (AH) {
            const unsigned* au = (const unsigned*)&aU;
            #pragma unroll
            for (int j = 0; j < 4; j++)
                As[(a_mt * 32 + a_laneg * 4 + j) * 4 + a_regrow + 2 * a_kreg] = au[j];
        } else {
            As[(a_mt * 32 + a_laneg * 4 + 0) * 4 + a_regrow + 2 * a_kreg] = pack_h2(aR0.x, aR0.y);
            As[(a_mt * 32 + a_laneg * 4 + 1) * 4 + a_regrow + 2 * a_kreg] = pack_h2(aR0.z, aR0.w);
            As[(a_mt * 32 + a_laneg * 4 + 2) * 4 + a_regrow + 2 * a_kreg] = pack_h2(aR1.x, aR1.y);
            As[(a_mt * 32 + a_laneg * 4 + 3) * 4 + a_regrow + 2 * a_kreg] = pack_h2(aR1.z, aR1.w);
        }
        Bs[((b_pair * 32 + b_g * 4 + b_t4)     * 2 + b_sub) * 2 + b_reg] = bU.x;
        Bs[((b_pair * 32 + b_g * 4 + b_t4 + 1) * 2 + b_sub) * 2 + b_reg] = bU.y;
        __syncthreads();

        if (kt + 16 < K) {
            if (AH) aU = avalid ? *(const uint4*)(Aph + kt + 16) : zu4;
            else {
                aR0 = avalid ? *(const float4*)(Apf + kt + 16)     : zf4;
                aR1 = avalid ? *(const float4*)(Apf + kt + 16 + 4) : zf4;
            }
            bU = bvalid ? *(const uint2*)(Wp + kt + 16) : zu2;
        }

        uint4 aF[2], bF[2];
        #pragma unroll
        for (int mt = 0; mt < 2; mt++)
            aF[mt] = *(const uint4*)&As[((wm * 2 + mt) * 32 + lane) * 4];
        #pragma unroll
        for (int np = 0; np < 2; np++)
            bF[np] = *(const uint4*)&Bs[((wn * 2 + np) * 32 + lane) * 4];

        #pragma unroll
        for (int mt = 0; mt < 2; mt++) {
            #pragma unroll
            for (int nt = 0; nt < 4; nt++) {
                int np = nt >> 1, sub = nt & 1;
                unsigned bh0 = sub ? bF[np].z : bF[np].x;
                unsigned bh1 = sub ? bF[np].w : bF[np].y;
                float* c = acc[mt][nt];
                mma_f16(c[0], c[1], c[2], c[3],
                        aF[mt].x, aF[mt].y, aF[mt].z, aF[mt].w, bh0, bh1);
            }
        }
        __syncthreads();
    }

    int g = lane >> 2, t4 = lane & 3;
    #pragma unroll
    for (int mt = 0; mt < 2; mt++) {
        #pragma unroll
        for (int nt = 0; nt < 4; nt++) {
            int r = row0 + wm * 32 + mt * 16 + g;
            int c = col0 + wn * 32 + nt * 8 + t4 * 2;
            if (c >= N) continue;
            float b0 = bias[c], b1 = bias[c + 1];
            #pragma unroll
            for (int half = 0; half < 2; half++) {
                int rr = r + half * 8;
                if (rr >= M) continue;
                float v0 = acc[mt][nt][half * 2 + 0] + b0;
                float v1 = acc[mt][nt][half * 2 + 1] + b1;
                if (epi == 1) { v0 = fmaxf(v0, 0.f); v1 = fmaxf(v1, 0.f); }
                else if (epi == 2) {
                    const float* rp = resid + (size_t)rr * ldc + coloff + c;
                    v0 += rp[0]; v1 += rp[1];
                }
                else if (epi == 3 && mask[rr]) { v0 = 0.f; v1 = 0.f; }
                if (OH) {
                    __half2 o = __floats2half2_rn(v0, v1);
                    *(__half2*)((__half*)Cv + (size_t)rr * ldc + coloff + c) = o;
                } else {
                    float2 o; o.x = v0; o.y = v1;
                    *(float2*)((float*)Cv + (size_t)rr * ldc + coloff + c) = o;
                }
            }
        }
    }
}

// ---------------- Self-attention (split-k flash: 2 threads per q) ----------
__global__ void __launch_bounds__(256) attn_kernel(
    const float* __restrict__ qkv, float* __restrict__ sa)
{
    int b = blockIdx.x / H_;
    int h = blockIdx.x % H_;
    int q0 = blockIdx.y * 128;
    extern __shared__ float sm[];
    float* Ks = sm;
    float* Vs = sm + NQ_ * DH_;
    int tid = threadIdx.x;

    for (int i = tid; i < NQ_ * DH_; i += 256) {
        int r = i >> 5, d = i & 31;
        const float* base = qkv + ((size_t)(b * NQ_ + r)) * 768 + h * 32 + d;
        Ks[i] = base[256];
        Vs[i] = base[512];
    }
    __syncthreads();

    int q  = q0 + (tid >> 1);
    int hf = tid & 1;

    float m = -1e30f, s = 0.f;
    float acc[32];
    #pragma unroll
    for (int d = 0; d < 32; d++) acc[d] = 0.f;

    if (q < NQ_) {
        float4 qv[8];
        const float4* qb = (const float4*)(qkv + ((size_t)(b * NQ_ + q)) * 768 + h * 32);
        #pragma unroll
        for (int u = 0; u < 8; u++) qv[u] = qb[u];

        int kbeg = hf * 150, kend = kbeg + 150;
        for (int k = kbeg; k < kend; k++) {
            const float4* kb = (const float4*)(Ks + k * 32);
            float dot = 0.f;
            #pragma unroll
            for (int u = 0; u < 8; u++) {
                float4 kv = kb[u];
                dot += qv[u].x * kv.x + qv[u].y * kv.y + qv[u].z * kv.z + qv[u].w * kv.w;
            }
            dot *= 0.17677669529663687f;   // 1/sqrt(32)
            float nm = fmaxf(m, dot);
            float corr = __expf(m - nm);
            float e = __expf(dot - nm);
            s = s * corr + e;
            const float4* vb = (const float4*)(Vs + k * 32);
            #pragma unroll
            for (int u = 0; u < 8; u++) {
                float4 vv = vb[u];
                acc[4*u+0] = acc[4*u+0] * corr + e * vv.x;
                acc[4*u+1] = acc[4*u+1] * corr + e * vv.y;
                acc[4*u+2] = acc[4*u+2] * corr + e * vv.z;
                acc[4*u+3] = acc[4*u+3] * corr + e * vv.w;
            }
            m = nm;
        }
    }

    float m_o = __shfl_xor_sync(0xffffffffu, m, 1);
    float s_o = __shfl_xor_sync(0xffffffffu, s, 1);
    float nm  = fmaxf(m, m_o);
    float es  = __expf(m - nm);
    float eo  = __expf(m_o - nm);
    float denom = s * es + s_o * eo;
    float inv = 1.f / denom;

    float* outp = sa + ((size_t)(b * NQ_ + q)) * C_ + h * 32;
    #pragma unroll
    for (int d = 0; d < 32; d++) {
        float t = acc[d] * es + __shfl_xor_sync(0xffffffffu, acc[d], 1) * eo;
        if (q < NQ_ && (d >> 4) == hf) outp[d] = t * inv;
    }
}

// ---------------- Deformable sampling (fp16 v, fp16 ca out) ----------------
__global__ void __launch_bounds__(256) deform_kernel(
    const __half* __restrict__ v, const float* __restrict__ offb,
    const float* __restrict__ awb, const float* __restrict__ refp,
    __half* __restrict__ ca)
{
    int bq = blockIdx.x;
    int h = threadIdx.x >> 5;
    int lane = threadIdx.x & 31;

    float lg = (lane < 12) ? awb[(size_t)bq * 96 + h * 12 + lane] : -INFINITY;
    float mx = lg;
    #pragma unroll
    for (int o = 16; o; o >>= 1) mx = fmaxf(mx, __shfl_xor_sync(0xffffffffu, mx, o));
    float e = (lane < 12) ? __expf(lg - mx) : 0.f;
    float ssum = e;
    #pragma unroll
    for (int o = 16; o; o >>= 1) ssum += __shfl_xor_sync(0xffffffffu, ssum, o);
    float myaw = e / ssum;

    const int Wl[3] = {128, 64, 32};
    const int Hl[3] = {128, 64, 32};
    const int st[3] = {0, 16384, 20480};

    float acc = 0.f;
    const float* offrow = offb + (size_t)bq * 192 + h * 24;
    const float* refrow = refp + (size_t)bq * 6;
    int bbase = (bq / NQ_) * LEN_IN_;

    #pragma unroll
    for (int l = 0; l < 3; l++) {
        float Wf = (float)Wl[l], Hf = (float)Hl[l];
        float rx = refrow[l * 2 + 0];
        float ry = refrow[l * 2 + 1];
        #pragma unroll
        for (int p = 0; p < 4; p++) {
            float ox = offrow[(l * 4 + p) * 2 + 0];
            float oy = offrow[(l * 4 + p) * 2 + 1];
            float lx = rx + ox / Wf;
            float ly = ry + oy / Hf;
            float x = lx * Wf - 0.5f;
            float y = ly * Hf - 0.5f;
            float x0 = floorf(x), y0 = floorf(y);
            float fx = x - x0, fy = y - y0;
            int ix = (int)x0, iy = (int)y0;
            float a = __shfl_sync(0xffffffffu, myaw, l * 4 + p);
            #pragma unroll
            for (int dy = 0; dy < 2; dy++) {
                int yi = iy + dy;
                if (yi < 0 || yi >= Hl[l]) continue;
                float wy = dy ? fy : (1.f - fy);
                #pragma unroll
                for (int dx = 0; dx < 2; dx++) {
                    int xi = ix + dx;
                    if (xi < 0 || xi >= Wl[l]) continue;
                    float w = wy * (dx ? fx : (1.f - fx));
                    int pos = st[l] + yi * Wl[l] + xi;
                    acc += a * w * __half2float(
                        v[((size_t)(bbase + pos) * H_ + h) * DH_ + lane]);
                }
            }
        }
    }
    ca[(size_t)bq * C_ + h * DH_ + lane] = __float2half_rn(acc);
}

// ---------------------------------------------------------------------------
extern "C" void kernel_launch(void* const* d_in, const int* in_sizes, int n_in,
                              void* d_out, int out_size)
{
    const float* tgt        = (const float*)d_in[0];
    const float* memory     = (const float*)d_in[1];
    const float* query_pos  = (const float*)d_in[3];
    const float* qref       = (const float*)d_in[5];
    const unsigned char* kpm = (const unsigned char*)d_in[7];
    const float* ln1g = (const float*)d_in[9];
    const float* ln1b = (const float*)d_in[10];
    const float* ln2g = (const float*)d_in[11];
    const float* ln2b = (const float*)d_in[12];
    const float* ln3g = (const float*)d_in[13];
    const float* ln3b = (const float*)d_in[14];
    const float* attn_in_w  = (const float*)d_in[15];
    const float* attn_in_b  = (const float*)d_in[16];
    const float* attn_out_w = (const float*)d_in[17];
    const float* attn_out_b = (const float*)d_in[18];
    const float* off_w  = (const float*)d_in[19];
    const float* off_b  = (const float*)d_in[20];
    const float* aw_w   = (const float*)d_in[21];
    const float* aw_b   = (const float*)d_in[22];
    const float* vproj_w = (const float*)d_in[23];
    const float* vproj_b = (const float*)d_in[24];
    const float* oproj_w = (const float*)d_in[25];
    const float* oproj_b = (const float*)d_in[26];
    const float* ffn1_w = (const float*)d_in[27];
    const float* ffn1_b = (const float*)d_in[28];
    const float* ffn2_w = (const float*)d_in[29];
    const float* ffn2_b = (const float*)d_in[30];
    float* out = (float*)d_out;

    float *p_qkv, *p_sa, *p_tgt1, *p_tgt2, *p_off, *p_aw;
    __half *p_vh, *p_cah, *p_t2h, *p_qkh, *p_hidh;
    __half *p_wqkvh, *p_wouth, *p_woffh, *p_wawh, *p_woh, *p_wvh, *p_w1h, *p_w2h;
    cudaGetSymbolAddress((void**)&p_qkv,  g_qkv);
    cudaGetSymbolAddress((void**)&p_sa,   g_sa);
    cudaGetSymbolAddress((void**)&p_tgt1, g_tgt1);
    cudaGetSymbolAddress((void**)&p_tgt2, g_tgt2);
    cudaGetSymbolAddress((void**)&p_off,  g_off);
    cudaGetSymbolAddress((void**)&p_aw,   g_aw);
    cudaGetSymbolAddress((void**)&p_vh,   g_vh);
    cudaGetSymbolAddress((void**)&p_cah,  g_cah);
    cudaGetSymbolAddress((void**)&p_t2h,  g_t2h);
    cudaGetSymbolAddress((void**)&p_qkh,  g_qkh);
    cudaGetSymbolAddress((void**)&p_hidh, g_hidh);
    cudaGetSymbolAddress((void**)&p_wqkvh, g_wqkvh);
    cudaGetSymbolAddress((void**)&p_wouth, g_wouth);
    cudaGetSymbolAddress((void**)&p_woffh, g_woffh);
    cudaGetSymbolAddress((void**)&p_wawh,  g_wawh);
    cudaGetSymbolAddress((void**)&p_woh,   g_woh);
    cudaGetSymbolAddress((void**)&p_wvh,   g_wvh);
    cudaGetSymbolAddress((void**)&p_w1h,   g_w1h);
    cudaGetSymbolAddress((void**)&p_w2h,   g_w2h);

    int attn_smem = NQ_ * DH_ * 2 * sizeof(float);   // 76800
    cudaFuncSetAttribute(attn_kernel, cudaFuncAttributeMaxDynamicSharedMemorySize, attn_smem);

    dim3 blk(256);
    const int MT_TILES = (MTGT + 127) / 128;   // 38
    const int MV_TILES = MV / 128;             // 2688

    // 0) weight fp16 conversions
    cvt_kernel<<<(3*C_*C_/4 + 255)/256, blk>>>(attn_in_w,  p_wqkvh, 3*C_*C_);
    cvt_kernel<<<(C_*C_/4 + 255)/256,   blk>>>(attn_out_w, p_wouth, C_*C_);
    cvt_kernel<<<(192*C_/4 + 255)/256,  blk>>>(off_w,      p_woffh, 192*C_);
    cvt_kernel<<<(96*C_/4 + 255)/256,   blk>>>(aw_w,       p_wawh,  96*C_);
    cvt_kernel<<<(C_*C_/4 + 255)/256,   blk>>>(oproj_w,    p_woh,   C_*C_);
    cvt_kernel<<<(C_*C_/4 + 255)/256,   blk>>>(vproj_w,    p_wvh,   C_*C_);
    cvt_kernel<<<(DFF_*C_/4 + 255)/256, blk>>>(ffn1_w,     p_w1h,   DFF_*C_);
    cvt_kernel<<<(C_*DFF_/4 + 255)/256, blk>>>(ffn2_w,     p_w2h,   C_*DFF_);

    // 1) LN1 -> t2h, qkh = LN(tgt) + query_pos
    ln_kernel<<<MTGT, blk>>>(tgt, ln1g, ln1b, query_pos, p_t2h, p_qkh);

    // 2) Q,K = qkh @ Wqk^T ; V = t2h @ Wv^T  (into qkv fp32, ldc=768)
    gemm_f16v<true,false><<<dim3(8, MT_TILES), blk>>>(p_qkh, p_wqkvh, attn_in_b,
        nullptr, nullptr, p_qkv, MTGT, 512, C_, 768, 0, 0);
    gemm_f16v<true,false><<<dim3(4, MT_TILES), blk>>>(p_t2h, p_wqkvh + 512*C_,
        attn_in_b + 512, nullptr, nullptr, p_qkv, MTGT, 256, C_, 768, 512, 0);

    // 3) self-attention -> sa
    attn_kernel<<<dim3(B_ * H_, 3), blk, attn_smem>>>(p_qkv, p_sa);

    // 4) tgt1 = tgt + sa @ attn_out_w^T + b
    gemm_f16v<false,false><<<dim3(4, MT_TILES), blk>>>(p_sa, p_wouth, attn_out_b,
        tgt, nullptr, p_tgt1, MTGT, C_, C_, C_, 0, 2);

    // 5) LN2 -> t2h
    ln_kernel<<<MTGT, blk>>>(p_tgt1, ln2g, ln2b, nullptr, p_t2h, nullptr);

    // 6) v = memory @ vproj^T + b, masked -> fp16
    gemm_f16v<false,true><<<dim3(4, MV_TILES), blk>>>(memory, p_wvh, vproj_b,
        nullptr, kpm, p_vh, MV, C_, C_, C_, 0, 3);

    // 7) offsets and attention-weight logits (fp32 out)
    gemm_f16v<true,false><<<dim3(3, MT_TILES), blk>>>(p_t2h, p_woffh, off_b,
        nullptr, nullptr, p_off, MTGT, 192, C_, 192, 0, 0);
    gemm_f16v<true,false><<<dim3(2, MT_TILES), blk>>>(p_t2h, p_wawh, aw_b,
        nullptr, nullptr, p_aw, MTGT, 96, C_, 96, 0, 0);

    // 8) deformable sampling -> cah (fp16)
    deform_kernel<<<MTGT, blk>>>(p_vh, p_off, p_aw, qref, p_cah);

    // 9) tgt2 = tgt1 + cah @ oproj^T + b
    gemm_f16v<true,false><<<dim3(4, MT_TILES), blk>>>(p_cah, p_woh, oproj_b,
        p_tgt1, nullptr, p_tgt2, MTGT, C_, C_, C_, 0, 2);

    // 10) LN3 -> t2h
    ln_kernel<<<MTGT, blk>>>(p_tgt2, ln3g, ln3b, nullptr, p_t2h, nullptr);

    // 11) FFN
    gemm_f16v<true,true><<<dim3(DFF_/64, MT_TILES), blk>>>(p_t2h, p_w1h, ffn1_b,
        nullptr, nullptr, p_hidh, MTGT, DFF_, C_, DFF_, 0, 1);
    gemm_f16v<true,false><<<dim3(4, MT_TILES), blk>>>(p_hidh, p_w2h, ffn2_b,
        p_tgt2, nullptr, out, MTGT, C_, DFF_, C_, 0, 2);
}